// round 7
// baseline (speedup 1.0000x reference)
#include <cuda_runtime.h>
#include <cuda_bf16.h>
#include <math.h>
#include <stdint.h>

#define NCONF 8192
#define NT 64
#define NX 64

// Precomputed rolled-W fragment tables: [T0][kk][nt][lane] -> uint2 (b0,b1)
// b0 = bf16x2( W[(16kk+(l&3)*2   +T0)&63][n], W[(16kk+(l&3)*2+1 +T0)&63][n] )
// b1 = same with k+8,k+9 ;  n = 8*nt + (l>>2)
__device__ uint2 BhiV[64 * 4 * 8 * 32];
__device__ uint2 BloV[64 * 4 * 8 * 32];

static __device__ __forceinline__ uint32_t pack_hi2(float x, float y) {
    uint32_t r;
    asm("cvt.rn.bf16x2.f32 %0, %1, %2;" : "=r"(r) : "f"(y), "f"(x)); // lo16=bf16(x)
    return r;
}
static __device__ __forceinline__ void cvt_split(float x, float y,
                                                 uint32_t& hi, uint32_t& lo) {
    uint32_t h = pack_hi2(x, y);
    float hx = __uint_as_float(h << 16);
    float hy = __uint_as_float(h & 0xffff0000u);
    lo = pack_hi2(x - hx, y - hy);
    hi = h;
}

static __device__ __forceinline__ void mma_bf16(float* d, uint32_t a0, uint32_t a1,
                                                uint32_t a2, uint32_t a3,
                                                uint32_t b0, uint32_t b1) {
    asm volatile(
        "mma.sync.aligned.m16n8k16.row.col.f32.bf16.bf16.f32 "
        "{%0,%1,%2,%3}, {%4,%5,%6,%7}, {%8,%9}, {%0,%1,%2,%3};"
        : "+f"(d[0]), "+f"(d[1]), "+f"(d[2]), "+f"(d[3])
        : "r"(a0), "r"(a1), "r"(a2), "r"(a3), "r"(b0), "r"(b1));
}

// ---------------------------------------------------------------------------
// Prep kernel: 64 blocks, one rolled-W variant each (fragment-ordered bf16 hi/lo)
// ---------------------------------------------------------------------------
__global__ void __launch_bounds__(64) prep_kernel(const float* __restrict__ W) {
    int T0 = blockIdx.x;
    for (int idx = threadIdx.x; idx < 1024; idx += 64) {
        int lane = idx & 31;
        int nt   = (idx >> 5) & 7;
        int kk   = idx >> 8;
        int n    = 8 * nt + (lane >> 2);
        int k0   = 16 * kk + (lane & 3) * 2;
        float w00 = W[(((k0     + T0) & 63) << 6) + n];
        float w01 = W[(((k0 + 1 + T0) & 63) << 6) + n];
        float w10 = W[(((k0 + 8 + T0) & 63) << 6) + n];
        float w11 = W[(((k0 + 9 + T0) & 63) << 6) + n];
        uint32_t h0, l0, h1, l1;
        cvt_split(w00, w01, h0, l0);
        cvt_split(w10, w11, h1, l1);
        BhiV[T0 * 1024 + idx] = make_uint2(h0, h1);
        BloV[T0 * 1024 + idx] = make_uint2(l0, l1);
    }
}

// ---------------------------------------------------------------------------
// Main kernel: 256 threads. Blocks 0..4095 -> 2 configs (warp w: cfg=w>>2,
// t-rows 16*(w&3)..+15). Block 4096 -> LU(W) log|det| + logDet tail.
// Zero smem / zero syncthreads in the GEMM path.
// ---------------------------------------------------------------------------
__global__ void __launch_bounds__(256, 3) main_kernel(
    const float* __restrict__ phi, const float* __restrict__ W,
    const float* __restrict__ b, float* __restrict__ out, int write_logdet)
{
    int tid  = threadIdx.x;
    int wid  = tid >> 5;
    int lane = tid & 31;

    if (blockIdx.x == NCONF / 2) {   // ---------------- LU block ----------------
        __shared__ float A[64][65];
        __shared__ float m[64];
        __shared__ float rv[2];
        __shared__ int   ri[2];
        __shared__ float sld;

        for (int idx = tid; idx < 64 * 64; idx += 256)
            A[idx >> 6][idx & 63] = W[idx];
        __syncthreads();

        float ld = 0.0f;
        for (int k = 0; k < 64; ++k) {
            if (tid < 64) {
                float v  = (tid >= k) ? fabsf(A[tid][k]) : -1.0f;
                int   vi = tid;
                #pragma unroll
                for (int off = 16; off > 0; off >>= 1) {
                    float ov = __shfl_down_sync(0xffffffffu, v,  off);
                    int   oi = __shfl_down_sync(0xffffffffu, vi, off);
                    if (ov > v) { v = ov; vi = oi; }
                }
                if ((tid & 31) == 0) { rv[tid >> 5] = v; ri[tid >> 5] = vi; }
            }
            __syncthreads();
            int p = (rv[1] > rv[0]) ? ri[1] : ri[0];
            if (tid < 64 && p != k) {
                float t1 = A[k][tid], t2 = A[p][tid];
                A[k][tid] = t2; A[p][tid] = t1;
            }
            __syncthreads();
            float piv = A[k][k];
            if (tid < 64) {
                ld += logf(fabsf(piv));
                if (tid > k) m[tid] = A[tid][k] / piv;
            }
            __syncthreads();
            if (tid < 64 && tid > k) {
                float akj = A[k][tid];
                for (int r = k + 1; r < 64; ++r)
                    A[r][tid] -= m[r] * akj;
            }
            __syncthreads();
        }
        if (write_logdet) {
            if (tid == 0) sld = ld;
            __syncthreads();
            float val = (float)NT * sld;
            float* tail = out + (size_t)NCONF * NT * NX;
            for (int idx = tid; idx < NCONF; idx += 256)
                tail[idx] = val;
        }
        return;
    }

    // ---------------- GEMM: warp w -> config i0+(w>>2), rows 16*(w&3)..+15 ----
    int i0  = blockIdx.x * 2;
    int cfg = wid >> 2;
    int qua = wid & 3;
    const float* phic = phi + (size_t)(i0 + cfg) * (NT * NX);

    // --- T0 (per-warp redundant; xor-reduce leaves result in all lanes) ---
    int T0;
    {
        float2 v0 = *reinterpret_cast<const float2*>(phic + (size_t)lane * NX);
        float2 v1 = *reinterpret_cast<const float2*>(phic + (size_t)(lane + 32) * NX);
        float b0 = fabsf(v0.x); int j0 = lane;
        float c0 = fabsf(v1.x);
        if (c0 < b0) { b0 = c0; j0 = lane + 32; }
        float b1 = fabsf(v0.y); int j1 = lane;
        float c1 = fabsf(v1.y);
        if (c1 < b1) { b1 = c1; j1 = lane + 32; }
        #pragma unroll
        for (int off = 16; off > 0; off >>= 1) {
            float ob = __shfl_xor_sync(0xffffffffu, b0, off);
            int   oj = __shfl_xor_sync(0xffffffffu, j0, off);
            if (ob < b0 || (ob == b0 && oj < j0)) { b0 = ob; j0 = oj; }
            ob = __shfl_xor_sync(0xffffffffu, b1, off);
            oj = __shfl_xor_sync(0xffffffffu, j1, off);
            if (ob < b1 || (ob == b1 && oj < j1)) { b1 = ob; j1 = oj; }
        }
        T0 = (j0 > j1) ? j1 : j0;
    }
    int offs = (64 - T0) & 63;

    float d[8][4];
    #pragma unroll
    for (int nt = 0; nt < 8; ++nt)
        #pragma unroll
        for (int e = 0; e < 4; ++e) d[nt][e] = 0.0f;

    // per-lane A base: row = 16*qua + (l>>2), col = (l&3)*2
    const float* aLane = phic + (size_t)(16 * qua + (lane >> 2)) * NX + (lane & 3) * 2;
    const uint2* bhBase = BhiV + T0 * 1024 + lane;
    const uint2* blBase = BloV + T0 * 1024 + lane;

    #pragma unroll
    for (int kk = 0; kk < 4; ++kk) {
        float2 v0 = *reinterpret_cast<const float2*>(aLane + 16 * kk);
        float2 v1 = *reinterpret_cast<const float2*>(aLane + 16 * kk + 8 * NX);
        float2 v2 = *reinterpret_cast<const float2*>(aLane + 16 * kk + 8);
        float2 v3 = *reinterpret_cast<const float2*>(aLane + 16 * kk + 8 * NX + 8);
        uint32_t ahi[4], alo[4];
        cvt_split(v0.x, v0.y, ahi[0], alo[0]);
        cvt_split(v1.x, v1.y, ahi[1], alo[1]);
        cvt_split(v2.x, v2.y, ahi[2], alo[2]);
        cvt_split(v3.x, v3.y, ahi[3], alo[3]);

        const uint2* bh = bhBase + kk * 256;
        const uint2* bl = blBase + kk * 256;
        #pragma unroll
        for (int nt = 0; nt < 8; ++nt) {
            uint2 h = bh[nt * 32];
            uint2 l = bl[nt * 32];
            mma_bf16(d[nt], ahi[0], ahi[1], ahi[2], ahi[3], h.x, h.y);
            mma_bf16(d[nt], alo[0], alo[1], alo[2], alo[3], h.x, h.y);
            mma_bf16(d[nt], ahi[0], ahi[1], ahi[2], ahi[3], l.x, l.y);
        }
    }

    // --- epilogue: +bias(j'), rolled scalar stores ---
    int qrow = lane >> 2;
    int qcol = (lane & 3) * 2;
    float* obase = out + (size_t)(i0 + cfg) * (NT * NX);
    int t0r = 16 * qua + qrow;
    float* orow0 = obase + (size_t)t0r * NX;
    float* orow1 = obase + (size_t)(t0r + 8) * NX;

    #pragma unroll
    for (int nt = 0; nt < 8; ++nt) {
        int jp0 = 8 * nt + qcol;
        float2 bias = *reinterpret_cast<const float2*>(b + jp0);
        int j0 = (jp0 + offs) & 63;
        int j1 = (jp0 + 1 + offs) & 63;
        orow0[j0] = d[nt][0] + bias.x;
        orow0[j1] = d[nt][1] + bias.y;
        orow1[j0] = d[nt][2] + bias.x;
        orow1[j1] = d[nt][3] + bias.y;
    }
}

// ---------------------------------------------------------------------------
extern "C" void kernel_launch(void* const* d_in, const int* in_sizes, int n_in,
                              void* d_out, int out_size) {
    const float* phi = nullptr;
    const float* W   = nullptr;
    const float* b   = nullptr;
    for (int k = 0; k < n_in; ++k) {
        if      (in_sizes[k] == NCONF * NT * NX) phi = (const float*)d_in[k];
        else if (in_sizes[k] == NX * NX)         W   = (const float*)d_in[k];
        else if (in_sizes[k] == NX)              b   = (const float*)d_in[k];
    }
    float* out = (float*)d_out;
    int write_logdet = (out_size >= NCONF * NT * NX + NCONF) ? 1 : 0;

    prep_kernel<<<64, 64>>>(W);
    main_kernel<<<NCONF / 2 + 1, 256>>>(phi, W, b, out, write_logdet);
}

// round 9
// speedup vs baseline: 1.1656x; 1.1656x over previous
#include <cuda_runtime.h>
#include <cuda_bf16.h>
#include <math.h>
#include <stdint.h>

#define NCONF 8192
#define NT 64
#define NX 64

// Fused rolled-W fragment table: [T0][kk][nt][lane] -> uint4(hi0, hi1, lo0, lo1)
// hi0 = bf16x2( W[(16kk+(l&3)*2 +T0)&63][n], W[(16kk+(l&3)*2+1 +T0)&63][n] )
// hi1 = same rows +8 ; lo* = residuals ; n = 8*nt + (l>>2)
__device__ uint4 BV[64 * 4 * 8 * 32];   // 1 MB

// -------- dynamic smem layout (bytes) --------
#define SM_B      0        // uint4 sB[2][1024] = 32768
#define SM_T0     32768    // 2 ints (pad to 128)
#define SM_STAGE  32896    // float stage[4][32][68] = 34816  (68*4=272B, 16-aligned)
#define SM_TOTAL  67712

static __device__ __forceinline__ uint32_t pack_hi2(float x, float y) {
    uint32_t r;
    asm("cvt.rn.bf16x2.f32 %0, %1, %2;" : "=r"(r) : "f"(y), "f"(x)); // lo16=bf16(x)
    return r;
}
static __device__ __forceinline__ void cvt_split(float x, float y,
                                                 uint32_t& hi, uint32_t& lo) {
    uint32_t h = pack_hi2(x, y);
    float hx = __uint_as_float(h << 16);
    float hy = __uint_as_float(h & 0xffff0000u);
    lo = pack_hi2(x - hx, y - hy);
    hi = h;
}
static __device__ __forceinline__ void mma_bf16(float* d, uint32_t a0, uint32_t a1,
                                                uint32_t a2, uint32_t a3,
                                                uint32_t b0, uint32_t b1) {
    asm volatile(
        "mma.sync.aligned.m16n8k16.row.col.f32.bf16.bf16.f32 "
        "{%0,%1,%2,%3}, {%4,%5,%6,%7}, {%8,%9}, {%0,%1,%2,%3};"
        : "+f"(d[0]), "+f"(d[1]), "+f"(d[2]), "+f"(d[3])
        : "r"(a0), "r"(a1), "r"(a2), "r"(a3), "r"(b0), "r"(b1));
}

// ---------------------------------------------------------------------------
__global__ void __launch_bounds__(64) prep_kernel(const float* __restrict__ W) {
    int T0 = blockIdx.x;
    for (int idx = threadIdx.x; idx < 1024; idx += 64) {
        int lane = idx & 31;
        int nt   = (idx >> 5) & 7;
        int kk   = idx >> 8;
        int n    = 8 * nt + (lane >> 2);
        int k0   = 16 * kk + (lane & 3) * 2;
        float w00 = W[(((k0     + T0) & 63) << 6) + n];
        float w01 = W[(((k0 + 1 + T0) & 63) << 6) + n];
        float w10 = W[(((k0 + 8 + T0) & 63) << 6) + n];
        float w11 = W[(((k0 + 9 + T0) & 63) << 6) + n];
        uint32_t h0, l0, h1, l1;
        cvt_split(w00, w01, h0, l0);
        cvt_split(w10, w11, h1, l1);
        BV[T0 * 1024 + idx] = make_uint4(h0, h1, l0, l1);
    }
}

// ---------------------------------------------------------------------------
// Main kernel: 128 threads. Blocks 0..4095: 2 configs (warp w: cfg=w>>1,
// rows 32*(w&1)..+31). Block 4096: LU(W) + logDet tail.
// ---------------------------------------------------------------------------
__global__ void __launch_bounds__(128, 3) main_kernel(
    const float* __restrict__ phi, const float* __restrict__ W,
    const float* __restrict__ b, float* __restrict__ out, int write_logdet)
{
    extern __shared__ char smem[];
    int tid  = threadIdx.x;
    int wid  = tid >> 5;
    int lane = tid & 31;

    if (blockIdx.x == NCONF / 2) {   // ---------------- LU block ----------------
        float (*A)[65] = reinterpret_cast<float(*)[65]>(smem);
        float* m   = reinterpret_cast<float*>(smem + 16640);
        float* rv  = reinterpret_cast<float*>(smem + 16896);
        int*   ri  = reinterpret_cast<int*>(smem + 16904);
        float* sld = reinterpret_cast<float*>(smem + 16912);

        for (int idx = tid; idx < 64 * 64; idx += 128)
            A[idx >> 6][idx & 63] = W[idx];
        __syncthreads();

        float ld = 0.0f;
        for (int k = 0; k < 64; ++k) {
            if (tid < 64) {
                float v  = (tid >= k) ? fabsf(A[tid][k]) : -1.0f;
                int   vi = tid;
                #pragma unroll
                for (int off = 16; off > 0; off >>= 1) {
                    float ov = __shfl_down_sync(0xffffffffu, v,  off);
                    int   oi = __shfl_down_sync(0xffffffffu, vi, off);
                    if (ov > v) { v = ov; vi = oi; }
                }
                if ((tid & 31) == 0) { rv[tid >> 5] = v; ri[tid >> 5] = vi; }
            }
            __syncthreads();
            int p = (rv[1] > rv[0]) ? ri[1] : ri[0];
            if (tid < 64 && p != k) {
                float t1 = A[k][tid], t2 = A[p][tid];
                A[k][tid] = t2; A[p][tid] = t1;
            }
            __syncthreads();
            float piv = A[k][k];
            if (tid < 64) {
                ld += logf(fabsf(piv));
                if (tid > k) m[tid] = A[tid][k] / piv;
            }
            __syncthreads();
            if (tid < 64 && tid > k) {
                float akj = A[k][tid];
                for (int r = k + 1; r < 64; ++r)
                    A[r][tid] -= m[r] * akj;
            }
            __syncthreads();
        }
        if (write_logdet) {
            if (tid == 0) *sld = ld;
            __syncthreads();
            float val = (float)NT * (*sld);
            float* tail = out + (size_t)NCONF * NT * NX;
            for (int idx = tid; idx < NCONF; idx += 128)
                tail[idx] = val;
        }
        return;
    }

    uint4* sB  = reinterpret_cast<uint4*>(smem + SM_B);
    int*  sT0  = reinterpret_cast<int*>(smem + SM_T0);

    int i0   = blockIdx.x * 2;
    int cfg  = wid >> 1;
    int half = wid & 1;
    const float* phic = phi + (size_t)(i0 + cfg) * (NT * NX);

    // --- T0: warp 0 -> cfg0, warp 2 -> cfg1 ---
    if ((wid & 1) == 0) {
        const float* p = phi + (size_t)(i0 + (wid >> 1)) * (NT * NX);
        float2 v0 = *reinterpret_cast<const float2*>(p + (size_t)lane * NX);
        float2 v1 = *reinterpret_cast<const float2*>(p + (size_t)(lane + 32) * NX);
        float b0 = fabsf(v0.x); int j0 = lane;
        float c0 = fabsf(v1.x);
        if (c0 < b0) { b0 = c0; j0 = lane + 32; }
        float b1 = fabsf(v0.y); int j1 = lane;
        float c1 = fabsf(v1.y);
        if (c1 < b1) { b1 = c1; j1 = lane + 32; }
        #pragma unroll
        for (int off = 16; off > 0; off >>= 1) {
            float ob = __shfl_xor_sync(0xffffffffu, b0, off);
            int   oj = __shfl_xor_sync(0xffffffffu, j0, off);
            if (ob < b0 || (ob == b0 && oj < j0)) { b0 = ob; j0 = oj; }
            ob = __shfl_xor_sync(0xffffffffu, b1, off);
            oj = __shfl_xor_sync(0xffffffffu, j1, off);
            if (ob < b1 || (ob == b1 && oj < j1)) { b1 = ob; j1 = oj; }
        }
        if (lane == 0) sT0[wid >> 1] = (j0 > j1) ? j1 : j0;
    }
    __syncthreads();

    // --- copy the two needed B-variants into smem (coalesced LDG.128) ---
    {
        int c = tid >> 6;
        int r = tid & 63;
        const uint4* src = BV + sT0[c] * 1024 + r;
        uint4* dst = sB + c * 1024 + r;
        #pragma unroll
        for (int k = 0; k < 16; ++k)
            dst[k * 64] = src[k * 64];
    }
    __syncthreads();

    int T0   = sT0[cfg];
    int offs = (64 - T0) & 63;

    float d[2][8][4];
    #pragma unroll
    for (int mt = 0; mt < 2; ++mt)
        #pragma unroll
        for (int nt = 0; nt < 8; ++nt)
            #pragma unroll
            for (int e = 0; e < 4; ++e) d[mt][nt][e] = 0.0f;

    const float* aLane = phic + (size_t)(32 * half + (lane >> 2)) * NX + (lane & 3) * 2;
    const uint4* bBase = sB + cfg * 1024 + lane;

    #pragma unroll
    for (int kk = 0; kk < 4; ++kk) {
        uint32_t ahi[2][4], alo[2][4];
        #pragma unroll
        for (int mt = 0; mt < 2; ++mt) {
            const float* p = aLane + (size_t)(16 * mt) * NX + 16 * kk;
            float2 v0 = *reinterpret_cast<const float2*>(p);
            float2 v1 = *reinterpret_cast<const float2*>(p + 8 * NX);
            float2 v2 = *reinterpret_cast<const float2*>(p + 8);
            float2 v3 = *reinterpret_cast<const float2*>(p + 8 * NX + 8);
            cvt_split(v0.x, v0.y, ahi[mt][0], alo[mt][0]);
            cvt_split(v1.x, v1.y, ahi[mt][1], alo[mt][1]);
            cvt_split(v2.x, v2.y, ahi[mt][2], alo[mt][2]);
            cvt_split(v3.x, v3.y, ahi[mt][3], alo[mt][3]);
        }
        const uint4* bk = bBase + kk * 256;
        #pragma unroll
        for (int nt = 0; nt < 8; ++nt) {
            uint4 w = bk[nt * 32];
            #pragma unroll
            for (int mt = 0; mt < 2; ++mt) {
                mma_bf16(d[mt][nt], ahi[mt][0], ahi[mt][1], ahi[mt][2], ahi[mt][3], w.x, w.y);
                mma_bf16(d[mt][nt], alo[mt][0], alo[mt][1], alo[mt][2], alo[mt][3], w.x, w.y);
                mma_bf16(d[mt][nt], ahi[mt][0], ahi[mt][1], ahi[mt][2], ahi[mt][3], w.z, w.w);
            }
        }
    }

    // --- epilogue: +bias, roll in smem stage (stride 68 = 16B aligned), flush ---
    int qrow = lane >> 2;
    int qcol = (lane & 3) * 2;
    float* st = reinterpret_cast<float*>(smem + SM_STAGE) + wid * (32 * 68);

    #pragma unroll
    for (int mt = 0; mt < 2; ++mt) {
        #pragma unroll
        for (int nt = 0; nt < 8; ++nt) {
            int jb = 8 * nt + qcol;
            float2 bias = *reinterpret_cast<const float2*>(b + jb);
            int j0 = (jb + offs) & 63;
            int j1 = (jb + 1 + offs) & 63;
            int r0 = 16 * mt + qrow;
            st[r0 * 68 + j0]       = d[mt][nt][0] + bias.x;
            st[r0 * 68 + j1]       = d[mt][nt][1] + bias.y;
            st[(r0 + 8) * 68 + j0] = d[mt][nt][2] + bias.x;
            st[(r0 + 8) * 68 + j1] = d[mt][nt][3] + bias.y;
        }
    }
    __syncwarp();

    float* obase = out + (size_t)(i0 + cfg) * (NT * NX) + (size_t)(32 * half) * NX;
    #pragma unroll
    for (int it = 0; it < 16; ++it) {
        int r  = it * 2 + (lane >> 4);      // 0..31
        int c4 = (lane & 15) * 4;
        float4 v = *reinterpret_cast<const float4*>(st + r * 68 + c4);
        *reinterpret_cast<float4*>(obase + (size_t)r * NX + c4) = v;
    }
}

// ---------------------------------------------------------------------------
extern "C" void kernel_launch(void* const* d_in, const int* in_sizes, int n_in,
                              void* d_out, int out_size) {
    const float* phi = nullptr;
    const float* W   = nullptr;
    const float* b   = nullptr;
    for (int k = 0; k < n_in; ++k) {
        if      (in_sizes[k] == NCONF * NT * NX) phi = (const float*)d_in[k];
        else if (in_sizes[k] == NX * NX)         W   = (const float*)d_in[k];
        else if (in_sizes[k] == NX)              b   = (const float*)d_in[k];
    }
    float* out = (float*)d_out;
    int write_logdet = (out_size >= NCONF * NT * NX + NCONF) ? 1 : 0;

    cudaFuncSetAttribute(main_kernel, cudaFuncAttributeMaxDynamicSharedMemorySize, SM_TOTAL);
    prep_kernel<<<64, 64>>>(W);
    main_kernel<<<NCONF / 2 + 1, 128, SM_TOTAL>>>(phi, W, b, out, write_logdet);
}

// round 10
// speedup vs baseline: 1.2123x; 1.0400x over previous
#include <cuda_runtime.h>
#include <cuda_bf16.h>
#include <math.h>
#include <stdint.h>

#define NCONF 8192
#define NT 64
#define NX 64

// Fused rolled-W fragment table: [T0][kk][nt][lane] -> uint4(hi0, hi1, lo0, lo1)
__device__ uint4 BV[64 * 4 * 8 * 32];   // 1 MB (L2-resident)

// -------- dynamic smem layout (bytes) --------
// AH [128 rows][128B bf16]  at 0      (16384)
// AL [128 rows][128B bf16]  at 16384  (16384)
// sB uint4[2][1024]         at 32768  (32768)
// sT0                       at 65536
// stage (post-loop overlay) at 0      float[4][32][68] = 34816
#define SM_AH     0
#define SM_AL     16384
#define SM_B      32768
#define SM_T0     65536
#define SM_TOTAL  65664

static __device__ __forceinline__ uint32_t smem_u32(const void* p) {
    uint32_t a;
    asm("{ .reg .u64 t; cvta.to.shared.u64 t, %1; cvt.u32.u64 %0, t; }" : "=r"(a) : "l"(p));
    return a;
}
static __device__ __forceinline__ uint32_t pack_hi2(float x, float y) {
    uint32_t r;
    asm("cvt.rn.bf16x2.f32 %0, %1, %2;" : "=r"(r) : "f"(y), "f"(x)); // lo16=bf16(x)
    return r;
}
static __device__ __forceinline__ void cvt_split(float x, float y,
                                                 uint32_t& hi, uint32_t& lo) {
    uint32_t h = pack_hi2(x, y);
    float hx = __uint_as_float(h << 16);
    float hy = __uint_as_float(h & 0xffff0000u);
    lo = pack_hi2(x - hx, y - hy);
    hi = h;
}
static __device__ __forceinline__ void ldsm_x4(uint32_t& r0, uint32_t& r1,
                                               uint32_t& r2, uint32_t& r3, uint32_t addr) {
    asm volatile("ldmatrix.sync.aligned.m8n8.x4.shared.b16 {%0,%1,%2,%3}, [%4];"
                 : "=r"(r0), "=r"(r1), "=r"(r2), "=r"(r3) : "r"(addr));
}
static __device__ __forceinline__ void mma_bf16(float* d, uint32_t a0, uint32_t a1,
                                                uint32_t a2, uint32_t a3,
                                                uint32_t b0, uint32_t b1) {
    asm volatile(
        "mma.sync.aligned.m16n8k16.row.col.f32.bf16.bf16.f32 "
        "{%0,%1,%2,%3}, {%4,%5,%6,%7}, {%8,%9}, {%0,%1,%2,%3};"
        : "+f"(d[0]), "+f"(d[1]), "+f"(d[2]), "+f"(d[3])
        : "r"(a0), "r"(a1), "r"(a2), "r"(a3), "r"(b0), "r"(b1));
}

// ---------------------------------------------------------------------------
__global__ void __launch_bounds__(64) prep_kernel(const float* __restrict__ W) {
    int T0 = blockIdx.x;
    for (int idx = threadIdx.x; idx < 1024; idx += 64) {
        int lane = idx & 31;
        int nt   = (idx >> 5) & 7;
        int kk   = idx >> 8;
        int n    = 8 * nt + (lane >> 2);
        int k0   = 16 * kk + (lane & 3) * 2;
        float w00 = W[(((k0     + T0) & 63) << 6) + n];
        float w01 = W[(((k0 + 1 + T0) & 63) << 6) + n];
        float w10 = W[(((k0 + 8 + T0) & 63) << 6) + n];
        float w11 = W[(((k0 + 9 + T0) & 63) << 6) + n];
        uint32_t h0, l0, h1, l1;
        cvt_split(w00, w01, h0, l0);
        cvt_split(w10, w11, h1, l1);
        BV[T0 * 1024 + idx] = make_uint4(h0, h1, l0, l1);
    }
}

// ---------------------------------------------------------------------------
// Main: 128 threads. Blocks 0..4095: 2 configs (warp w: cfg=w>>1, rows
// 32*(w&1)..+31). Block 4096: LU(W) + logDet tail.
// ---------------------------------------------------------------------------
__global__ void __launch_bounds__(128, 3) main_kernel(
    const float* __restrict__ phi, const float* __restrict__ W,
    const float* __restrict__ b, float* __restrict__ out, int write_logdet)
{
    extern __shared__ char smem[];
    uint32_t sbase = smem_u32(smem);
    int tid  = threadIdx.x;
    int wid  = tid >> 5;
    int lane = tid & 31;

    if (blockIdx.x == NCONF / 2) {   // ---------------- LU block ----------------
        float (*A)[65] = reinterpret_cast<float(*)[65]>(smem);
        float* m   = reinterpret_cast<float*>(smem + 16640);
        float* rv  = reinterpret_cast<float*>(smem + 16896);
        int*   ri  = reinterpret_cast<int*>(smem + 16904);
        float* sld = reinterpret_cast<float*>(smem + 16912);

        for (int idx = tid; idx < 64 * 64; idx += 128)
            A[idx >> 6][idx & 63] = W[idx];
        __syncthreads();

        float ld = 0.0f;
        for (int k = 0; k < 64; ++k) {
            if (tid < 64) {
                float v  = (tid >= k) ? fabsf(A[tid][k]) : -1.0f;
                int   vi = tid;
                #pragma unroll
                for (int off = 16; off > 0; off >>= 1) {
                    float ov = __shfl_down_sync(0xffffffffu, v,  off);
                    int   oi = __shfl_down_sync(0xffffffffu, vi, off);
                    if (ov > v) { v = ov; vi = oi; }
                }
                if ((tid & 31) == 0) { rv[tid >> 5] = v; ri[tid >> 5] = vi; }
            }
            __syncthreads();
            int p = (rv[1] > rv[0]) ? ri[1] : ri[0];
            if (tid < 64 && p != k) {
                float t1 = A[k][tid], t2 = A[p][tid];
                A[k][tid] = t2; A[p][tid] = t1;
            }
            __syncthreads();
            float piv = A[k][k];
            if (tid < 64) {
                ld += logf(fabsf(piv));
                if (tid > k) m[tid] = A[tid][k] / piv;
            }
            __syncthreads();
            if (tid < 64 && tid > k) {
                float akj = A[k][tid];
                for (int r = k + 1; r < 64; ++r)
                    A[r][tid] -= m[r] * akj;
            }
            __syncthreads();
        }
        if (write_logdet) {
            if (tid == 0) *sld = ld;
            __syncthreads();
            float val = (float)NT * (*sld);
            float* tail = out + (size_t)NCONF * NT * NX;
            for (int idx = tid; idx < NCONF; idx += 128)
                tail[idx] = val;
        }
        return;
    }

    uint4* sB = reinterpret_cast<uint4*>(smem + SM_B);
    int*  sT0 = reinterpret_cast<int*>(smem + SM_T0);

    int i0   = blockIdx.x * 2;
    int cfg  = wid >> 1;
    int half = wid & 1;

    // --- T0: warps 0,2 (cfg 0,1), from gmem cols 0,1 ---
    if ((wid & 1) == 0) {
        const float* p = phi + (size_t)(i0 + (wid >> 1)) * (NT * NX);
        float2 v0 = *reinterpret_cast<const float2*>(p + (size_t)lane * NX);
        float2 v1 = *reinterpret_cast<const float2*>(p + (size_t)(lane + 32) * NX);
        float b0 = fabsf(v0.x); int j0 = lane;
        float c0 = fabsf(v1.x);
        if (c0 < b0) { b0 = c0; j0 = lane + 32; }
        float b1 = fabsf(v0.y); int j1 = lane;
        float c1 = fabsf(v1.y);
        if (c1 < b1) { b1 = c1; j1 = lane + 32; }
        #pragma unroll
        for (int off = 16; off > 0; off >>= 1) {
            float ob = __shfl_xor_sync(0xffffffffu, b0, off);
            int   oj = __shfl_xor_sync(0xffffffffu, j0, off);
            if (ob < b0 || (ob == b0 && oj < j0)) { b0 = ob; j0 = oj; }
            ob = __shfl_xor_sync(0xffffffffu, b1, off);
            oj = __shfl_xor_sync(0xffffffffu, j1, off);
            if (ob < b1 || (ob == b1 && oj < j1)) { b1 = ob; j1 = oj; }
        }
        if (lane == 0) sT0[wid >> 1] = (j0 > j1) ? j1 : j0;
    }

    // --- A staging: coalesced float4 LDG -> bf16 hi/lo -> swizzled STS.64 ---
    {
        const float4* g4 = reinterpret_cast<const float4*>(phi + (size_t)i0 * (NT * NX));
        #pragma unroll
        for (int s = 0; s < 16; ++s) {
            int idx = tid + 128 * s;            // 0..2047
            float4 v = g4[idx];
            int mrow = idx >> 4;                // cfg*64 + t
            int q    = idx & 15;
            uint32_t off = (uint32_t)mrow * 128 +
                           ((uint32_t)((q >> 1) ^ (mrow & 7)) << 4) + ((q & 1) << 3);
            uint32_t hx, lx, hy, ly;
            cvt_split(v.x, v.y, hx, lx);
            cvt_split(v.z, v.w, hy, ly);
            *reinterpret_cast<uint2*>(smem + SM_AH + off) = make_uint2(hx, hy);
            *reinterpret_cast<uint2*>(smem + SM_AL + off) = make_uint2(lx, ly);
        }
    }
    __syncthreads();

    // --- B copy: two T0 variants, coalesced LDG.128 from L2-resident table ---
    {
        int c = tid >> 6;
        int r = tid & 63;
        const uint4* src = BV + sT0[c] * 1024 + r;
        uint4* dst = sB + c * 1024 + r;
        #pragma unroll
        for (int k = 0; k < 16; ++k)
            dst[k * 64] = src[k * 64];
    }
    __syncthreads();

    int T0   = sT0[cfg];
    int offs = (64 - T0) & 63;

    float d[2][8][4];
    #pragma unroll
    for (int mt = 0; mt < 2; ++mt)
        #pragma unroll
        for (int nt = 0; nt < 8; ++nt)
            #pragma unroll
            for (int e = 0; e < 4; ++e) d[mt][nt][e] = 0.0f;

    int mrel = (lane & 7) + ((lane >> 3) & 1) * 8;
    int csel = (lane >> 4) & 1;
    int rbase = cfg * 64 + 32 * half;
    const uint4* bBase = sB + cfg * 1024 + lane;

    #pragma unroll
    for (int kk = 0; kk < 4; ++kk) {
        uint32_t ahi[2][4], alo[2][4];
        #pragma unroll
        for (int mt = 0; mt < 2; ++mt) {
            int mm = rbase + 16 * mt + mrel;
            uint32_t co = (uint32_t)((kk * 2 + csel) ^ (mm & 7)) << 4;
            uint32_t rowoff = (uint32_t)mm * 128 + co;
            ldsm_x4(ahi[mt][0], ahi[mt][1], ahi[mt][2], ahi[mt][3], sbase + SM_AH + rowoff);
            ldsm_x4(alo[mt][0], alo[mt][1], alo[mt][2], alo[mt][3], sbase + SM_AL + rowoff);
        }
        const uint4* bk = bBase + kk * 256;
        #pragma unroll
        for (int nt = 0; nt < 8; ++nt) {
            uint4 w = bk[nt * 32];
            #pragma unroll
            for (int mt = 0; mt < 2; ++mt) {
                mma_bf16(d[mt][nt], ahi[mt][0], ahi[mt][1], ahi[mt][2], ahi[mt][3], w.x, w.y);
                mma_bf16(d[mt][nt], alo[mt][0], alo[mt][1], alo[mt][2], alo[mt][3], w.x, w.y);
                mma_bf16(d[mt][nt], ahi[mt][0], ahi[mt][1], ahi[mt][2], ahi[mt][3], w.z, w.w);
            }
        }
    }
    __syncthreads();   // all warps done with A/B smem before stage overlay

    // --- epilogue: +bias, roll into stage (stride 68), coalesced flush ---
    int qrow = lane >> 2;
    int qcol = (lane & 3) * 2;
    float* st = reinterpret_cast<float*>(smem) + wid * (32 * 68);

    #pragma unroll
    for (int mt = 0; mt < 2; ++mt) {
        #pragma unroll
        for (int nt = 0; nt < 8; ++nt) {
            int jb = 8 * nt + qcol;
            float2 bias = *reinterpret_cast<const float2*>(b + jb);
            int j0 = (jb + offs) & 63;
            int j1 = (jb + 1 + offs) & 63;
            int r0 = 16 * mt + qrow;
            st[r0 * 68 + j0]       = d[mt][nt][0] + bias.x;
            st[r0 * 68 + j1]       = d[mt][nt][1] + bias.y;
            st[(r0 + 8) * 68 + j0] = d[mt][nt][2] + bias.x;
            st[(r0 + 8) * 68 + j1] = d[mt][nt][3] + bias.y;
        }
    }
    __syncwarp();

    float* obase = out + (size_t)(i0 + cfg) * (NT * NX) + (size_t)(32 * half) * NX;
    #pragma unroll
    for (int it = 0; it < 16; ++it) {
        int r  = it * 2 + (lane >> 4);
        int c4 = (lane & 15) * 4;
        float4 v = *reinterpret_cast<const float4*>(st + r * 68 + c4);
        *reinterpret_cast<float4*>(obase + (size_t)r * NX + c4) = v;
    }
}

// ---------------------------------------------------------------------------
extern "C" void kernel_launch(void* const* d_in, const int* in_sizes, int n_in,
                              void* d_out, int out_size) {
    const float* phi = nullptr;
    const float* W   = nullptr;
    const float* b   = nullptr;
    for (int k = 0; k < n_in; ++k) {
        if      (in_sizes[k] == NCONF * NT * NX) phi = (const float*)d_in[k];
        else if (in_sizes[k] == NX * NX)         W   = (const float*)d_in[k];
        else if (in_sizes[k] == NX)              b   = (const float*)d_in[k];
    }
    float* out = (float*)d_out;
    int write_logdet = (out_size >= NCONF * NT * NX + NCONF) ? 1 : 0;

    cudaFuncSetAttribute(main_kernel, cudaFuncAttributeMaxDynamicSharedMemorySize, SM_TOTAL);
    prep_kernel<<<64, 64>>>(W);
    main_kernel<<<NCONF / 2 + 1, 128, SM_TOTAL>>>(phi, W, b, out, write_logdet);
}

// round 11
// speedup vs baseline: 1.2176x; 1.0043x over previous
#include <cuda_runtime.h>
#include <cuda_bf16.h>
#include <math.h>
#include <stdint.h>

#define NCONF 8192
#define NT 64
#define NX 64

// Fused rolled-W fragment table: [T0][kk][nt][lane] -> uint4(hi0, hi1, lo0, lo1)
__device__ uint4 BV[64 * 4 * 8 * 32];   // 1 MB (L2-resident)

// -------- dynamic smem layout (bytes), one config per CTA --------
// AH [64 rows][128B bf16]  at 0      (8192)
// AL [64 rows][128B bf16]  at 8192   (8192)
// sB uint4[1024]           at 16384  (16384)
// sT0                      at 32768
// stage overlay at 0: float[4][16][68] = 17408
#define SM_AH     0
#define SM_AL     8192
#define SM_B      16384
#define SM_T0     32768
#define SM_TOTAL  32896

static __device__ __forceinline__ uint32_t smem_u32(const void* p) {
    uint32_t a;
    asm("{ .reg .u64 t; cvta.to.shared.u64 t, %1; cvt.u32.u64 %0, t; }" : "=r"(a) : "l"(p));
    return a;
}
static __device__ __forceinline__ uint32_t pack_hi2(float x, float y) {
    uint32_t r;
    asm("cvt.rn.bf16x2.f32 %0, %1, %2;" : "=r"(r) : "f"(y), "f"(x)); // lo16=bf16(x)
    return r;
}
static __device__ __forceinline__ void cvt_split(float x, float y,
                                                 uint32_t& hi, uint32_t& lo) {
    uint32_t h = pack_hi2(x, y);
    float hx = __uint_as_float(h << 16);
    float hy = __uint_as_float(h & 0xffff0000u);
    lo = pack_hi2(x - hx, y - hy);
    hi = h;
}
static __device__ __forceinline__ void ldsm_x4(uint32_t& r0, uint32_t& r1,
                                               uint32_t& r2, uint32_t& r3, uint32_t addr) {
    asm volatile("ldmatrix.sync.aligned.m8n8.x4.shared.b16 {%0,%1,%2,%3}, [%4];"
                 : "=r"(r0), "=r"(r1), "=r"(r2), "=r"(r3) : "r"(addr));
}
static __device__ __forceinline__ void mma_bf16(float* d, uint32_t a0, uint32_t a1,
                                                uint32_t a2, uint32_t a3,
                                                uint32_t b0, uint32_t b1) {
    asm volatile(
        "mma.sync.aligned.m16n8k16.row.col.f32.bf16.bf16.f32 "
        "{%0,%1,%2,%3}, {%4,%5,%6,%7}, {%8,%9}, {%0,%1,%2,%3};"
        : "+f"(d[0]), "+f"(d[1]), "+f"(d[2]), "+f"(d[3])
        : "r"(a0), "r"(a1), "r"(a2), "r"(a3), "r"(b0), "r"(b1));
}

// ---------------------------------------------------------------------------
__global__ void __launch_bounds__(64) prep_kernel(const float* __restrict__ W) {
    int T0 = blockIdx.x;
    for (int idx = threadIdx.x; idx < 1024; idx += 64) {
        int lane = idx & 31;
        int nt   = (idx >> 5) & 7;
        int kk   = idx >> 8;
        int n    = 8 * nt + (lane >> 2);
        int k0   = 16 * kk + (lane & 3) * 2;
        float w00 = W[(((k0     + T0) & 63) << 6) + n];
        float w01 = W[(((k0 + 1 + T0) & 63) << 6) + n];
        float w10 = W[(((k0 + 8 + T0) & 63) << 6) + n];
        float w11 = W[(((k0 + 9 + T0) & 63) << 6) + n];
        uint32_t h0, l0, h1, l1;
        cvt_split(w00, w01, h0, l0);
        cvt_split(w10, w11, h1, l1);
        BV[T0 * 1024 + idx] = make_uint4(h0, h1, l0, l1);
    }
}

// ---------------------------------------------------------------------------
// Main: 128 threads, ONE config per CTA (warp w: rows 16w..16w+15).
// Block 8192: LU(W) + logDet tail.
// ---------------------------------------------------------------------------
__global__ void __launch_bounds__(128, 5) main_kernel(
    const float* __restrict__ phi, const float* __restrict__ W,
    const float* __restrict__ b, float* __restrict__ out, int write_logdet)
{
    extern __shared__ char smem[];
    uint32_t sbase = smem_u32(smem);
    int tid  = threadIdx.x;
    int wid  = tid >> 5;
    int lane = tid & 31;

    if (blockIdx.x == NCONF) {   // ---------------- LU block ----------------
        float (*A)[65] = reinterpret_cast<float(*)[65]>(smem);   // 16640 <= 32896
        float* m   = reinterpret_cast<float*>(smem + 16640);
        float* rv  = reinterpret_cast<float*>(smem + 16896);
        int*   ri  = reinterpret_cast<int*>(smem + 16904);
        float* sld = reinterpret_cast<float*>(smem + 16912);

        for (int idx = tid; idx < 64 * 64; idx += 128)
            A[idx >> 6][idx & 63] = W[idx];
        __syncthreads();

        float ld = 0.0f;
        for (int k = 0; k < 64; ++k) {
            if (tid < 64) {
                float v  = (tid >= k) ? fabsf(A[tid][k]) : -1.0f;
                int   vi = tid;
                #pragma unroll
                for (int off = 16; off > 0; off >>= 1) {
                    float ov = __shfl_down_sync(0xffffffffu, v,  off);
                    int   oi = __shfl_down_sync(0xffffffffu, vi, off);
                    if (ov > v) { v = ov; vi = oi; }
                }
                if ((tid & 31) == 0) { rv[tid >> 5] = v; ri[tid >> 5] = vi; }
            }
            __syncthreads();
            int p = (rv[1] > rv[0]) ? ri[1] : ri[0];
            if (tid < 64 && p != k) {
                float t1 = A[k][tid], t2 = A[p][tid];
                A[k][tid] = t2; A[p][tid] = t1;
            }
            __syncthreads();
            float piv = A[k][k];
            if (tid < 64) {
                ld += logf(fabsf(piv));
                if (tid > k) m[tid] = A[tid][k] / piv;
            }
            __syncthreads();
            if (tid < 64 && tid > k) {
                float akj = A[k][tid];
                for (int r = k + 1; r < 64; ++r)
                    A[r][tid] -= m[r] * akj;
            }
            __syncthreads();
        }
        if (write_logdet) {
            if (tid == 0) *sld = ld;
            __syncthreads();
            float val = (float)NT * (*sld);
            float* tail = out + (size_t)NCONF * NT * NX;
            for (int idx = tid; idx < NCONF; idx += 128)
                tail[idx] = val;
        }
        return;
    }

    uint4* sB = reinterpret_cast<uint4*>(smem + SM_B);
    int*  sT0 = reinterpret_cast<int*>(smem + SM_T0);

    int i = blockIdx.x;
    const float* phic = phi + (size_t)i * (NT * NX);

    // --- T0 (warp 0) ---
    if (wid == 0) {
        float2 v0 = *reinterpret_cast<const float2*>(phic + (size_t)lane * NX);
        float2 v1 = *reinterpret_cast<const float2*>(phic + (size_t)(lane + 32) * NX);
        float b0 = fabsf(v0.x); int j0 = lane;
        float c0 = fabsf(v1.x);
        if (c0 < b0) { b0 = c0; j0 = lane + 32; }
        float b1 = fabsf(v0.y); int j1 = lane;
        float c1 = fabsf(v1.y);
        if (c1 < b1) { b1 = c1; j1 = lane + 32; }
        #pragma unroll
        for (int off = 16; off > 0; off >>= 1) {
            float ob = __shfl_xor_sync(0xffffffffu, b0, off);
            int   oj = __shfl_xor_sync(0xffffffffu, j0, off);
            if (ob < b0 || (ob == b0 && oj < j0)) { b0 = ob; j0 = oj; }
            ob = __shfl_xor_sync(0xffffffffu, b1, off);
            oj = __shfl_xor_sync(0xffffffffu, j1, off);
            if (ob < b1 || (ob == b1 && oj < j1)) { b1 = ob; j1 = oj; }
        }
        if (lane == 0) sT0[0] = (j0 > j1) ? j1 : j0;
    }

    // --- A staging: coalesced float4 LDG -> bf16 hi/lo -> swizzled STS.64 ---
    {
        const float4* g4 = reinterpret_cast<const float4*>(phic);
        #pragma unroll
        for (int s = 0; s < 8; ++s) {
            int idx = tid + 128 * s;            // 0..1023
            float4 v = g4[idx];
            int mrow = idx >> 4;                // t (0..63)
            int q    = idx & 15;
            uint32_t off = (uint32_t)mrow * 128 +
                           ((uint32_t)((q >> 1) ^ (mrow & 7)) << 4) + ((q & 1) << 3);
            uint32_t hx, lx, hy, ly;
            cvt_split(v.x, v.y, hx, lx);
            cvt_split(v.z, v.w, hy, ly);
            *reinterpret_cast<uint2*>(smem + SM_AH + off) = make_uint2(hx, hy);
            *reinterpret_cast<uint2*>(smem + SM_AL + off) = make_uint2(lx, ly);
        }
    }
    __syncthreads();

    int T0   = sT0[0];
    int offs = (64 - T0) & 63;

    // --- B copy (all threads, 8 uint4 each from L2-resident table) ---
    {
        const uint4* src = BV + T0 * 1024 + tid;
        #pragma unroll
        for (int k = 0; k < 8; ++k)
            sB[tid + k * 128] = src[k * 128];
    }

    // preload bias into regs (hides const latency under barrier)
    int qrow = lane >> 2;
    int qcol = (lane & 3) * 2;
    float2 bias[8];
    #pragma unroll
    for (int nt = 0; nt < 8; ++nt)
        bias[nt] = *reinterpret_cast<const float2*>(b + 8 * nt + qcol);
    __syncthreads();

    // --- MMA loop: warp handles rows 16*wid..+15 (mt=1) ---
    float d[8][4];
    #pragma unroll
    for (int nt = 0; nt < 8; ++nt)
        #pragma unroll
        for (int e = 0; e < 4; ++e) d[nt][e] = 0.0f;

    int mrel = (lane & 7) + ((lane >> 3) & 1) * 8;
    int csel = (lane >> 4) & 1;
    int mm   = 16 * wid + mrel;
    const uint4* bBase = sB + lane;

    #pragma unroll
    for (int kk = 0; kk < 4; ++kk) {
        uint32_t co = (uint32_t)((kk * 2 + csel) ^ (mm & 7)) << 4;
        uint32_t rowoff = (uint32_t)mm * 128 + co;
        uint32_t ahi[4], alo[4];
        ldsm_x4(ahi[0], ahi[1], ahi[2], ahi[3], sbase + SM_AH + rowoff);
        ldsm_x4(alo[0], alo[1], alo[2], alo[3], sbase + SM_AL + rowoff);
        const uint4* bk = bBase + kk * 256;
        #pragma unroll
        for (int nt = 0; nt < 8; ++nt) {
            uint4 w = bk[nt * 32];
            mma_bf16(d[nt], ahi[0], ahi[1], ahi[2], ahi[3], w.x, w.y);
            mma_bf16(d[nt], alo[0], alo[1], alo[2], alo[3], w.x, w.y);
            mma_bf16(d[nt], ahi[0], ahi[1], ahi[2], ahi[3], w.z, w.w);
        }
    }
    __syncthreads();   // all warps done with A/B smem before stage overlay

    // --- epilogue: +bias, roll into stage (stride 68), coalesced flush ---
    float* st = reinterpret_cast<float*>(smem) + wid * (16 * 68);
    #pragma unroll
    for (int nt = 0; nt < 8; ++nt) {
        int jb = 8 * nt + qcol;
        int j0 = (jb + offs) & 63;
        int j1 = (jb + 1 + offs) & 63;
        st[qrow * 68 + j0]       = d[nt][0] + bias[nt].x;
        st[qrow * 68 + j1]       = d[nt][1] + bias[nt].y;
        st[(qrow + 8) * 68 + j0] = d[nt][2] + bias[nt].x;
        st[(qrow + 8) * 68 + j1] = d[nt][3] + bias[nt].y;
    }
    __syncwarp();

    float* obase = out + (size_t)i * (NT * NX) + (size_t)(16 * wid) * NX;
    #pragma unroll
    for (int it = 0; it < 8; ++it) {
        int r  = it * 2 + (lane >> 4);      // 0..15
        int c4 = (lane & 15) * 4;
        float4 v = *reinterpret_cast<const float4*>(st + r * 68 + c4);
        *reinterpret_cast<float4*>(obase + (size_t)r * NX + c4) = v;
    }
}

// ---------------------------------------------------------------------------
extern "C" void kernel_launch(void* const* d_in, const int* in_sizes, int n_in,
                              void* d_out, int out_size) {
    const float* phi = nullptr;
    const float* W   = nullptr;
    const float* b   = nullptr;
    for (int k = 0; k < n_in; ++k) {
        if      (in_sizes[k] == NCONF * NT * NX) phi = (const float*)d_in[k];
        else if (in_sizes[k] == NX * NX)         W   = (const float*)d_in[k];
        else if (in_sizes[k] == NX)              b   = (const float*)d_in[k];
    }
    float* out = (float*)d_out;
    int write_logdet = (out_size >= NCONF * NT * NX + NCONF) ? 1 : 0;

    cudaFuncSetAttribute(main_kernel, cudaFuncAttributeMaxDynamicSharedMemorySize, SM_TOTAL);
    prep_kernel<<<64, 64>>>(W);
    main_kernel<<<NCONF + 1, 128, SM_TOTAL>>>(phi, W, b, out, write_logdet);
}

// round 12
// speedup vs baseline: 1.2420x; 1.0200x over previous
#include <cuda_runtime.h>
#include <cuda_bf16.h>
#include <math.h>
#include <stdint.h>

#define NCONF 8192
#define NT 64
#define NX 64

// Fused rolled-W fragment table: [T0][kk][nt][lane] -> uint4(hi0, hi1, lo0, lo1)
// Already in the exact bf16 per-lane fragment format the MMA loop consumes,
// so CTAs can cp.async it straight into smem.
__device__ uint4 BV[64 * 4 * 8 * 32];   // 1 MB (L2-resident)

// -------- dynamic smem layout (bytes), one config per CTA --------
// AH [64 rows][128B bf16]  at 0      (8192)
// AL [64 rows][128B bf16]  at 8192   (8192)
// sB uint4[1024]           at 16384  (16384)
// stage overlay at 0: float[4][16][68] = 17408
#define SM_AH     0
#define SM_AL     8192
#define SM_B      16384
#define SM_TOTAL  32768

static __device__ __forceinline__ uint32_t smem_u32(const void* p) {
    uint32_t a;
    asm("{ .reg .u64 t; cvta.to.shared.u64 t, %1; cvt.u32.u64 %0, t; }" : "=r"(a) : "l"(p));
    return a;
}
static __device__ __forceinline__ uint32_t pack_hi2(float x, float y) {
    uint32_t r;
    asm("cvt.rn.bf16x2.f32 %0, %1, %2;" : "=r"(r) : "f"(y), "f"(x)); // lo16=bf16(x)
    return r;
}
static __device__ __forceinline__ void cvt_split(float x, float y,
                                                 uint32_t& hi, uint32_t& lo) {
    uint32_t h = pack_hi2(x, y);
    float hx = __uint_as_float(h << 16);
    float hy = __uint_as_float(h & 0xffff0000u);
    lo = pack_hi2(x - hx, y - hy);
    hi = h;
}
static __device__ __forceinline__ void ldsm_x4(uint32_t& r0, uint32_t& r1,
                                               uint32_t& r2, uint32_t& r3, uint32_t addr) {
    asm volatile("ldmatrix.sync.aligned.m8n8.x4.shared.b16 {%0,%1,%2,%3}, [%4];"
                 : "=r"(r0), "=r"(r1), "=r"(r2), "=r"(r3) : "r"(addr));
}
static __device__ __forceinline__ void mma_bf16(float* d, uint32_t a0, uint32_t a1,
                                                uint32_t a2, uint32_t a3,
                                                uint32_t b0, uint32_t b1) {
    asm volatile(
        "mma.sync.aligned.m16n8k16.row.col.f32.bf16.bf16.f32 "
        "{%0,%1,%2,%3}, {%4,%5,%6,%7}, {%8,%9}, {%0,%1,%2,%3};"
        : "+f"(d[0]), "+f"(d[1]), "+f"(d[2]), "+f"(d[3])
        : "r"(a0), "r"(a1), "r"(a2), "r"(a3), "r"(b0), "r"(b1));
}

// ---------------------------------------------------------------------------
__global__ void __launch_bounds__(64) prep_kernel(const float* __restrict__ W) {
    int T0 = blockIdx.x;
    for (int idx = threadIdx.x; idx < 1024; idx += 64) {
        int lane = idx & 31;
        int nt   = (idx >> 5) & 7;
        int kk   = idx >> 8;
        int n    = 8 * nt + (lane >> 2);
        int k0   = 16 * kk + (lane & 3) * 2;
        float w00 = W[(((k0     + T0) & 63) << 6) + n];
        float w01 = W[(((k0 + 1 + T0) & 63) << 6) + n];
        float w10 = W[(((k0 + 8 + T0) & 63) << 6) + n];
        float w11 = W[(((k0 + 9 + T0) & 63) << 6) + n];
        uint32_t h0, l0, h1, l1;
        cvt_split(w00, w01, h0, l0);
        cvt_split(w10, w11, h1, l1);
        BV[T0 * 1024 + idx] = make_uint4(h0, h1, l0, l1);
    }
}

// ---------------------------------------------------------------------------
// Main: 128 threads, ONE config per CTA (warp w: rows 16w..16w+15,
// warp-private A staging). Block 8192: LU(W) + logDet tail.
// ---------------------------------------------------------------------------
__global__ void __launch_bounds__(128, 5) main_kernel(
    const float* __restrict__ phi, const float* __restrict__ W,
    const float* __restrict__ b, float* __restrict__ out, int write_logdet)
{
    extern __shared__ char smem[];
    uint32_t sbase = smem_u32(smem);
    int tid  = threadIdx.x;
    int wid  = tid >> 5;
    int lane = tid & 31;

    if (blockIdx.x == NCONF) {   // ---------------- LU block ----------------
        float (*A)[65] = reinterpret_cast<float(*)[65]>(smem);
        float* m   = reinterpret_cast<float*>(smem + 16640);
        float* rv  = reinterpret_cast<float*>(smem + 16896);
        int*   ri  = reinterpret_cast<int*>(smem + 16904);
        float* sld = reinterpret_cast<float*>(smem + 16912);

        for (int idx = tid; idx < 64 * 64; idx += 128)
            A[idx >> 6][idx & 63] = W[idx];
        __syncthreads();

        float ld = 0.0f;
        for (int k = 0; k < 64; ++k) {
            if (tid < 64) {
                float v  = (tid >= k) ? fabsf(A[tid][k]) : -1.0f;
                int   vi = tid;
                #pragma unroll
                for (int off = 16; off > 0; off >>= 1) {
                    float ov = __shfl_down_sync(0xffffffffu, v,  off);
                    int   oi = __shfl_down_sync(0xffffffffu, vi, off);
                    if (ov > v) { v = ov; vi = oi; }
                }
                if ((tid & 31) == 0) { rv[tid >> 5] = v; ri[tid >> 5] = vi; }
            }
            __syncthreads();
            int p = (rv[1] > rv[0]) ? ri[1] : ri[0];
            if (tid < 64 && p != k) {
                float t1 = A[k][tid], t2 = A[p][tid];
                A[k][tid] = t2; A[p][tid] = t1;
            }
            __syncthreads();
            float piv = A[k][k];
            if (tid < 64) {
                ld += logf(fabsf(piv));
                if (tid > k) m[tid] = A[tid][k] / piv;
            }
            __syncthreads();
            if (tid < 64 && tid > k) {
                float akj = A[k][tid];
                for (int r = k + 1; r < 64; ++r)
                    A[r][tid] -= m[r] * akj;
            }
            __syncthreads();
        }
        if (write_logdet) {
            if (tid == 0) *sld = ld;
            __syncthreads();
            float val = (float)NT * (*sld);
            float* tail = out + (size_t)NCONF * NT * NX;
            for (int idx = tid; idx < NCONF; idx += 128)
                tail[idx] = val;
        }
        return;
    }

    int i = blockIdx.x;
    const float* phic = phi + (size_t)i * (NT * NX);

    // --- T0: every warp computes it redundantly (no barrier, no smem) ---
    int T0;
    {
        float2 v0 = *reinterpret_cast<const float2*>(phic + (size_t)lane * NX);
        float2 v1 = *reinterpret_cast<const float2*>(phic + (size_t)(lane + 32) * NX);
        float b0 = fabsf(v0.x); int j0 = lane;
        float c0 = fabsf(v1.x);
        if (c0 < b0) { b0 = c0; j0 = lane + 32; }
        float b1 = fabsf(v0.y); int j1 = lane;
        float c1 = fabsf(v1.y);
        if (c1 < b1) { b1 = c1; j1 = lane + 32; }
        #pragma unroll
        for (int off = 16; off > 0; off >>= 1) {
            float ob = __shfl_xor_sync(0xffffffffu, b0, off);
            int   oj = __shfl_xor_sync(0xffffffffu, j0, off);
            if (ob < b0 || (ob == b0 && oj < j0)) { b0 = ob; j0 = oj; }
            ob = __shfl_xor_sync(0xffffffffu, b1, off);
            oj = __shfl_xor_sync(0xffffffffu, j1, off);
            if (ob < b1 || (ob == b1 && oj < j1)) { b1 = ob; j1 = oj; }
        }
        T0 = (j0 > j1) ? j1 : j0;
    }
    int offs = (64 - T0) & 63;

    // --- B: cp.async straight from fragment table (no regs, overlaps A stage)
    {
        uint32_t dstBase = sbase + SM_B;
        const uint4* src = BV + T0 * 1024 + tid;
        #pragma unroll
        for (int k2 = 0; k2 < 8; ++k2) {
            uint32_t dst = dstBase + (uint32_t)(tid + k2 * 128) * 16;
            asm volatile("cp.async.cg.shared.global [%0], [%1], 16;"
                         :: "r"(dst), "l"(__cvta_generic_to_global(src + k2 * 128)));
        }
        asm volatile("cp.async.commit_group;" ::: "memory");
    }

    // --- A staging, WARP-PRIVATE: warp w stages rows 16w..16w+15 only ---
    {
        const float4* g4 = reinterpret_cast<const float4*>(phic);
        #pragma unroll
        for (int s = 0; s < 8; ++s) {
            int idx = wid * 256 + 32 * s + lane;   // float4 index in this warp's rows
            float4 v = g4[idx];
            int mrow = idx >> 4;
            int q    = idx & 15;
            uint32_t off = (uint32_t)mrow * 128 +
                           ((uint32_t)((q >> 1) ^ (mrow & 7)) << 4) + ((q & 1) << 3);
            uint32_t hx, lx, hy, ly;
            cvt_split(v.x, v.y, hx, lx);
            cvt_split(v.z, v.w, hy, ly);
            *reinterpret_cast<uint2*>(smem + SM_AH + off) = make_uint2(hx, hy);
            *reinterpret_cast<uint2*>(smem + SM_AL + off) = make_uint2(lx, ly);
        }
    }

    // bias preload (hides const/gmem latency before the barrier)
    int qrow = lane >> 2;
    int qcol = (lane & 3) * 2;
    float2 bias[8];
    #pragma unroll
    for (int nt = 0; nt < 8; ++nt)
        bias[nt] = *reinterpret_cast<const float2*>(b + 8 * nt + qcol);

    __syncwarp();                                        // own A rows visible
    asm volatile("cp.async.wait_group 0;" ::: "memory"); // own B slices landed
    __syncthreads();                                     // all B slices visible

    // --- MMA loop: warp handles rows 16*wid..+15 ---
    uint4* sB = reinterpret_cast<uint4*>(smem + SM_B);
    float d[8][4];
    #pragma unroll
    for (int nt = 0; nt < 8; ++nt)
        #pragma unroll
        for (int e = 0; e < 4; ++e) d[nt][e] = 0.0f;

    int mrel = (lane & 7) + ((lane >> 3) & 1) * 8;
    int csel = (lane >> 4) & 1;
    int mm   = 16 * wid + mrel;
    const uint4* bBase = sB + lane;

    #pragma unroll
    for (int kk = 0; kk < 4; ++kk) {
        uint32_t co = (uint32_t)((kk * 2 + csel) ^ (mm & 7)) << 4;
        uint32_t rowoff = (uint32_t)mm * 128 + co;
        uint32_t ahi[4], alo[4];
        ldsm_x4(ahi[0], ahi[1], ahi[2], ahi[3], sbase + SM_AH + rowoff);
        ldsm_x4(alo[0], alo[1], alo[2], alo[3], sbase + SM_AL + rowoff);
        const uint4* bk = bBase + kk * 256;
        #pragma unroll
        for (int nt = 0; nt < 8; ++nt) {
            uint4 w = bk[nt * 32];
            mma_bf16(d[nt], ahi[0], ahi[1], ahi[2], ahi[3], w.x, w.y);
            mma_bf16(d[nt], alo[0], alo[1], alo[2], alo[3], w.x, w.y);
            mma_bf16(d[nt], ahi[0], ahi[1], ahi[2], ahi[3], w.z, w.w);
        }
    }
    __syncthreads();   // A/B smem dead; stage overlay safe

    // --- epilogue: +bias, roll into stage (stride 68), coalesced flush ---
    float* st = reinterpret_cast<float*>(smem) + wid * (16 * 68);
    #pragma unroll
    for (int nt = 0; nt < 8; ++nt) {
        int jb = 8 * nt + qcol;
        int j0 = (jb + offs) & 63;
        int j1 = (jb + 1 + offs) & 63;
        st[qrow * 68 + j0]       = d[nt][0] + bias[nt].x;
        st[qrow * 68 + j1]       = d[nt][1] + bias[nt].y;
        st[(qrow + 8) * 68 + j0] = d[nt][2] + bias[nt].x;
        st[(qrow + 8) * 68 + j1] = d[nt][3] + bias[nt].y;
    }
    __syncwarp();

    float* obase = out + (size_t)i * (NT * NX) + (size_t)(16 * wid) * NX;
    #pragma unroll
    for (int it = 0; it < 8; ++it) {
        int r  = it * 2 + (lane >> 4);
        int c4 = (lane & 15) * 4;
        float4 v = *reinterpret_cast<const float4*>(st + r * 68 + c4);
        *reinterpret_cast<float4*>(obase + (size_t)r * NX + c4) = v;
    }
}

// ---------------------------------------------------------------------------
extern "C" void kernel_launch(void* const* d_in, const int* in_sizes, int n_in,
                              void* d_out, int out_size) {
    const float* phi = nullptr;
    const float* W   = nullptr;
    const float* b   = nullptr;
    for (int k = 0; k < n_in; ++k) {
        if      (in_sizes[k] == NCONF * NT * NX) phi = (const float*)d_in[k];
        else if (in_sizes[k] == NX * NX)         W   = (const float*)d_in[k];
        else if (in_sizes[k] == NX)              b   = (const float*)d_in[k];
    }
    float* out = (float*)d_out;
    int write_logdet = (out_size >= NCONF * NT * NX + NCONF) ? 1 : 0;

    cudaFuncSetAttribute(main_kernel, cudaFuncAttributeMaxDynamicSharedMemorySize, SM_TOTAL);
    prep_kernel<<<64, 64>>>(W);
    main_kernel<<<NCONF + 1, 128, SM_TOTAL>>>(phi, W, b, out, write_logdet);
}

// round 13
// speedup vs baseline: 1.3424x; 1.0809x over previous
#include <cuda_runtime.h>
#include <cuda_bf16.h>
#include <math.h>
#include <stdint.h>

#define NCONF 8192
#define NT 64
#define NX 64

// Fused rolled-W fragment table: [T0][kk][nt][lane] -> uint4(hi0, hi1, lo0, lo1)
__device__ uint4 BV[64 * 4 * 8 * 32];   // 1 MB (L2-resident)

// -------- dynamic smem layout (bytes), one config per CTA --------
#define SM_AH     0        // [64 rows][128B bf16] 8192
#define SM_AL     8192     // 8192
#define SM_B      16384    // uint4[1024] 16384
#define SM_TOTAL  32768
// stage overlay at 0: float[4][16][68] = 17408

static __device__ __forceinline__ uint32_t smem_u32(const void* p) {
    uint32_t a;
    asm("{ .reg .u64 t; cvta.to.shared.u64 t, %1; cvt.u32.u64 %0, t; }" : "=r"(a) : "l"(p));
    return a;
}
static __device__ __forceinline__ uint32_t pack_hi2(float x, float y) {
    uint32_t r;
    asm("cvt.rn.bf16x2.f32 %0, %1, %2;" : "=r"(r) : "f"(y), "f"(x)); // lo16=bf16(x)
    return r;
}
static __device__ __forceinline__ void cvt_split(float x, float y,
                                                 uint32_t& hi, uint32_t& lo) {
    uint32_t h = pack_hi2(x, y);
    float hx = __uint_as_float(h << 16);
    float hy = __uint_as_float(h & 0xffff0000u);
    lo = pack_hi2(x - hx, y - hy);
    hi = h;
}
static __device__ __forceinline__ void ldsm_x4(uint32_t& r0, uint32_t& r1,
                                               uint32_t& r2, uint32_t& r3, uint32_t addr) {
    asm volatile("ldmatrix.sync.aligned.m8n8.x4.shared.b16 {%0,%1,%2,%3}, [%4];"
                 : "=r"(r0), "=r"(r1), "=r"(r2), "=r"(r3) : "r"(addr));
}
static __device__ __forceinline__ void mma_bf16(float* d, uint32_t a0, uint32_t a1,
                                                uint32_t a2, uint32_t a3,
                                                uint32_t b0, uint32_t b1) {
    asm volatile(
        "mma.sync.aligned.m16n8k16.row.col.f32.bf16.bf16.f32 "
        "{%0,%1,%2,%3}, {%4,%5,%6,%7}, {%8,%9}, {%0,%1,%2,%3};"
        : "+f"(d[0]), "+f"(d[1]), "+f"(d[2]), "+f"(d[3])
        : "r"(a0), "r"(a1), "r"(a2), "r"(a3), "r"(b0), "r"(b1));
}

// ---------------------------------------------------------------------------
__global__ void __launch_bounds__(64) prep_kernel(const float* __restrict__ W) {
    int T0 = blockIdx.x;
    for (int idx = threadIdx.x; idx < 1024; idx += 64) {
        int lane = idx & 31;
        int nt   = (idx >> 5) & 7;
        int kk   = idx >> 8;
        int n    = 8 * nt + (lane >> 2);
        int k0   = 16 * kk + (lane & 3) * 2;
        float w00 = W[(((k0     + T0) & 63) << 6) + n];
        float w01 = W[(((k0 + 1 + T0) & 63) << 6) + n];
        float w10 = W[(((k0 + 8 + T0) & 63) << 6) + n];
        float w11 = W[(((k0 + 9 + T0) & 63) << 6) + n];
        uint32_t h0, l0, h1, l1;
        cvt_split(w00, w01, h0, l0);
        cvt_split(w10, w11, h1, l1);
        BV[T0 * 1024 + idx] = make_uint4(h0, h1, l0, l1);
    }
}

// ---------------------------------------------------------------------------
// Main: 128 threads. Block 0: LU(W) + logDet tail (starts in wave 1, overlaps).
// Blocks 1..8192: config i = blockIdx.x - 1 (warp w: rows 16w..16w+15).
// ---------------------------------------------------------------------------
__global__ void __launch_bounds__(128, 6) main_kernel(
    const float* __restrict__ phi, const float* __restrict__ W,
    const float* __restrict__ b, float* __restrict__ out, int write_logdet)
{
    extern __shared__ char smem[];
    uint32_t sbase = smem_u32(smem);
    int tid  = threadIdx.x;
    int wid  = tid >> 5;
    int lane = tid & 31;

    if (blockIdx.x == 0) {   // ---------------- LU block ----------------
        float (*A)[65] = reinterpret_cast<float(*)[65]>(smem);
        float* m   = reinterpret_cast<float*>(smem + 16640);
        float* rv  = reinterpret_cast<float*>(smem + 16896);
        int*   ri  = reinterpret_cast<int*>(smem + 16904);
        float* sld = reinterpret_cast<float*>(smem + 16912);

        for (int idx = tid; idx < 64 * 64; idx += 128)
            A[idx >> 6][idx & 63] = W[idx];
        __syncthreads();

        float ld = 0.0f;
        for (int k = 0; k < 64; ++k) {
            if (tid < 64) {
                float v  = (tid >= k) ? fabsf(A[tid][k]) : -1.0f;
                int   vi = tid;
                #pragma unroll
                for (int off = 16; off > 0; off >>= 1) {
                    float ov = __shfl_down_sync(0xffffffffu, v,  off);
                    int   oi = __shfl_down_sync(0xffffffffu, vi, off);
                    if (ov > v) { v = ov; vi = oi; }
                }
                if ((tid & 31) == 0) { rv[tid >> 5] = v; ri[tid >> 5] = vi; }
            }
            __syncthreads();
            int p = (rv[1] > rv[0]) ? ri[1] : ri[0];
            if (tid < 64 && p != k) {
                float t1 = A[k][tid], t2 = A[p][tid];
                A[k][tid] = t2; A[p][tid] = t1;
            }
            __syncthreads();
            float piv = A[k][k];
            if (tid < 64) {
                ld += logf(fabsf(piv));
                if (tid > k) m[tid] = A[tid][k] / piv;
            }
            __syncthreads();
            if (tid < 64 && tid > k) {
                float akj = A[k][tid];
                for (int r = k + 1; r < 64; ++r)
                    A[r][tid] -= m[r] * akj;
            }
            __syncthreads();
        }
        if (write_logdet) {
            if (tid == 0) *sld = ld;
            __syncthreads();
            float val = (float)NT * (*sld);
            float* tail = out + (size_t)NCONF * NT * NX;
            for (int idx = tid; idx < NCONF; idx += 128)
                tail[idx] = val;
        }
        return;
    }

    int i = blockIdx.x - 1;
    const float* phic = phi + (size_t)i * (NT * NX);

    // --- T0: every warp computes it redundantly (no barrier, no smem) ---
    int T0;
    {
        float2 v0 = *reinterpret_cast<const float2*>(phic + (size_t)lane * NX);
        float2 v1 = *reinterpret_cast<const float2*>(phic + (size_t)(lane + 32) * NX);
        float b0 = fabsf(v0.x); int j0 = lane;
        float c0 = fabsf(v1.x);
        if (c0 < b0) { b0 = c0; j0 = lane + 32; }
        float b1 = fabsf(v0.y); int j1 = lane;
        float c1 = fabsf(v1.y);
        if (c1 < b1) { b1 = c1; j1 = lane + 32; }
        #pragma unroll
        for (int off = 16; off > 0; off >>= 1) {
            float ob = __shfl_xor_sync(0xffffffffu, b0, off);
            int   oj = __shfl_xor_sync(0xffffffffu, j0, off);
            if (ob < b0 || (ob == b0 && oj < j0)) { b0 = ob; j0 = oj; }
            ob = __shfl_xor_sync(0xffffffffu, b1, off);
            oj = __shfl_xor_sync(0xffffffffu, j1, off);
            if (ob < b1 || (ob == b1 && oj < j1)) { b1 = ob; j1 = oj; }
        }
        T0 = (j0 > j1) ? j1 : j0;
    }
    int offs = (64 - T0) & 63;

    // --- B: cp.async straight from fragment table (overlaps A staging) ---
    {
        uint32_t dstBase = sbase + SM_B;
        const uint4* src = BV + T0 * 1024 + tid;
        #pragma unroll
        for (int k2 = 0; k2 < 8; ++k2) {
            uint32_t dst = dstBase + (uint32_t)(tid + k2 * 128) * 16;
            asm volatile("cp.async.cg.shared.global [%0], [%1], 16;"
                         :: "r"(dst), "l"(__cvta_generic_to_global(src + k2 * 128)));
        }
        asm volatile("cp.async.commit_group;" ::: "memory");
    }

    // --- A staging, WARP-PRIVATE: warp w stages rows 16w..16w+15 ---
    {
        const float4* g4 = reinterpret_cast<const float4*>(phic);
        #pragma unroll
        for (int s = 0; s < 8; ++s) {
            int idx = wid * 256 + 32 * s + lane;
            float4 v = g4[idx];
            int mrow = idx >> 4;
            int q    = idx & 15;
            uint32_t off = (uint32_t)mrow * 128 +
                           ((uint32_t)((q >> 1) ^ (mrow & 7)) << 4) + ((q & 1) << 3);
            uint32_t hx, lx, hy, ly;
            cvt_split(v.x, v.y, hx, lx);
            cvt_split(v.z, v.w, hy, ly);
            *reinterpret_cast<uint2*>(smem + SM_AH + off) = make_uint2(hx, hy);
            *reinterpret_cast<uint2*>(smem + SM_AL + off) = make_uint2(lx, ly);
        }
    }

    __syncwarp();                                        // own A rows visible
    asm volatile("cp.async.wait_group 0;" ::: "memory"); // own B slices landed
    __syncthreads();                                     // all B slices visible

    // --- MMA loop: warp handles rows 16*wid..+15 ---
    uint4* sB = reinterpret_cast<uint4*>(smem + SM_B);
    float d[8][4];
    #pragma unroll
    for (int nt = 0; nt < 8; ++nt)
        #pragma unroll
        for (int e = 0; e < 4; ++e) d[nt][e] = 0.0f;

    int mrel = (lane & 7) + ((lane >> 3) & 1) * 8;
    int csel = (lane >> 4) & 1;
    int mm   = 16 * wid + mrel;
    const uint4* bBase = sB + lane;

    #pragma unroll
    for (int kk = 0; kk < 4; ++kk) {
        uint32_t co = (uint32_t)((kk * 2 + csel) ^ (mm & 7)) << 4;
        uint32_t rowoff = (uint32_t)mm * 128 + co;
        uint32_t ahi[4], alo[4];
        ldsm_x4(ahi[0], ahi[1], ahi[2], ahi[3], sbase + SM_AH + rowoff);
        ldsm_x4(alo[0], alo[1], alo[2], alo[3], sbase + SM_AL + rowoff);
        const uint4* bk = bBase + kk * 256;
        #pragma unroll
        for (int nt = 0; nt < 8; ++nt) {
            uint4 w = bk[nt * 32];
            mma_bf16(d[nt], ahi[0], ahi[1], ahi[2], ahi[3], w.x, w.y);
            mma_bf16(d[nt], alo[0], alo[1], alo[2], alo[3], w.x, w.y);
            mma_bf16(d[nt], ahi[0], ahi[1], ahi[2], ahi[3], w.z, w.w);
        }
    }
    __syncthreads();   // A/B smem dead; stage overlay safe

    // --- epilogue: +bias (loaded here; L1-resident), roll into stage, flush ---
    int qrow = lane >> 2;
    int qcol = (lane & 3) * 2;
    float* st = reinterpret_cast<float*>(smem) + wid * (16 * 68);
    #pragma unroll
    for (int nt = 0; nt < 8; ++nt) {
        int jb = 8 * nt + qcol;
        float2 bias = __ldg(reinterpret_cast<const float2*>(b + jb));
        int j0 = (jb + offs) & 63;
        int j1 = (jb + 1 + offs) & 63;
        st[qrow * 68 + j0]       = d[nt][0] + bias.x;
        st[qrow * 68 + j1]       = d[nt][1] + bias.y;
        st[(qrow + 8) * 68 + j0] = d[nt][2] + bias.x;
        st[(qrow + 8) * 68 + j1] = d[nt][3] + bias.y;
    }
    __syncwarp();

    float* obase = out + (size_t)i * (NT * NX) + (size_t)(16 * wid) * NX;
    #pragma unroll
    for (int it = 0; it < 8; ++it) {
        int r  = it * 2 + (lane >> 4);
        int c4 = (lane & 15) * 4;
        float4 v = *reinterpret_cast<const float4*>(st + r * 68 + c4);
        *reinterpret_cast<float4*>(obase + (size_t)r * NX + c4) = v;
    }
}

// ---------------------------------------------------------------------------
extern "C" void kernel_launch(void* const* d_in, const int* in_sizes, int n_in,
                              void* d_out, int out_size) {
    const float* phi = nullptr;
    const float* W   = nullptr;
    const float* b   = nullptr;
    for (int k = 0; k < n_in; ++k) {
        if      (in_sizes[k] == NCONF * NT * NX) phi = (const float*)d_in[k];
        else if (in_sizes[k] == NX * NX)         W   = (const float*)d_in[k];
        else if (in_sizes[k] == NX)              b   = (const float*)d_in[k];
    }
    float* out = (float*)d_out;
    int write_logdet = (out_size >= NCONF * NT * NX + NCONF) ? 1 : 0;

    cudaFuncSetAttribute(main_kernel, cudaFuncAttributeMaxDynamicSharedMemorySize, SM_TOTAL);
    prep_kernel<<<64, 64>>>(W);
    main_kernel<<<NCONF + 1, 128, SM_TOTAL>>>(phi, W, b, out, write_logdet);
}

// round 14
// speedup vs baseline: 1.4077x; 1.0486x over previous
#include <cuda_runtime.h>
#include <cuda_bf16.h>
#include <math.h>
#include <stdint.h>

#define NCONF 8192
#define NT 64
#define NX 64
#define GRIDC 888   // 148 SMs * 6 CTAs

// Fused rolled-W fragment table: [T0][kk][nt][lane] -> uint4(hi0, hi1, lo0, lo1)
__device__ uint4 BV[64 * 4 * 8 * 32];   // 1 MB (L2-resident)

// -------- dynamic smem layout (bytes) --------
// AH [64][128B] at 0 (8192), AL at 8192 (8192), pad to 17408
// stage overlay [0,17408) = float[4][16][68]
// sB uint4[1024] at 17408 (16384)  -- disjoint from stage
#define SM_AH     0
#define SM_AL     8192
#define SM_B      17408
#define SM_TOTAL  33792

static __device__ __forceinline__ uint32_t smem_u32(const void* p) {
    uint32_t a;
    asm("{ .reg .u64 t; cvta.to.shared.u64 t, %1; cvt.u32.u64 %0, t; }" : "=r"(a) : "l"(p));
    return a;
}
static __device__ __forceinline__ uint32_t pack_hi2(float x, float y) {
    uint32_t r;
    asm("cvt.rn.bf16x2.f32 %0, %1, %2;" : "=r"(r) : "f"(y), "f"(x)); // lo16=bf16(x)
    return r;
}
static __device__ __forceinline__ void cvt_split(float x, float y,
                                                 uint32_t& hi, uint32_t& lo) {
    uint32_t h = pack_hi2(x, y);
    float hx = __uint_as_float(h << 16);
    float hy = __uint_as_float(h & 0xffff0000u);
    lo = pack_hi2(x - hx, y - hy);
    hi = h;
}
static __device__ __forceinline__ void ldsm_x4(uint32_t& r0, uint32_t& r1,
                                               uint32_t& r2, uint32_t& r3, uint32_t addr) {
    asm volatile("ldmatrix.sync.aligned.m8n8.x4.shared.b16 {%0,%1,%2,%3}, [%4];"
                 : "=r"(r0), "=r"(r1), "=r"(r2), "=r"(r3) : "r"(addr));
}
static __device__ __forceinline__ void mma_bf16(float* d, uint32_t a0, uint32_t a1,
                                                uint32_t a2, uint32_t a3,
                                                uint32_t b0, uint32_t b1) {
    asm volatile(
        "mma.sync.aligned.m16n8k16.row.col.f32.bf16.bf16.f32 "
        "{%0,%1,%2,%3}, {%4,%5,%6,%7}, {%8,%9}, {%0,%1,%2,%3};"
        : "+f"(d[0]), "+f"(d[1]), "+f"(d[2]), "+f"(d[3])
        : "r"(a0), "r"(a1), "r"(a2), "r"(a3), "r"(b0), "r"(b1));
}
// warp-collective argmin pair -> T0 (result uniform across lanes)
static __device__ __forceinline__ int t0_reduce(float2 v0, float2 v1, int lane) {
    float b0 = fabsf(v0.x); int j0 = lane;
    float c0 = fabsf(v1.x);
    if (c0 < b0) { b0 = c0; j0 = lane + 32; }
    float b1 = fabsf(v0.y); int j1 = lane;
    float c1 = fabsf(v1.y);
    if (c1 < b1) { b1 = c1; j1 = lane + 32; }
    #pragma unroll
    for (int off = 16; off > 0; off >>= 1) {
        float ob = __shfl_xor_sync(0xffffffffu, b0, off);
        int   oj = __shfl_xor_sync(0xffffffffu, j0, off);
        if (ob < b0 || (ob == b0 && oj < j0)) { b0 = ob; j0 = oj; }
        ob = __shfl_xor_sync(0xffffffffu, b1, off);
        oj = __shfl_xor_sync(0xffffffffu, j1, off);
        if (ob < b1 || (ob == b1 && oj < j1)) { b1 = ob; j1 = oj; }
    }
    return (j0 > j1) ? j1 : j0;
}
static __device__ __forceinline__ void b_issue(uint32_t sbase, int T0, int tid) {
    uint32_t dstBase = sbase + SM_B;
    const uint4* src = BV + T0 * 1024 + tid;
    #pragma unroll
    for (int k2 = 0; k2 < 8; ++k2) {
        uint32_t dst = dstBase + (uint32_t)(tid + k2 * 128) * 16;
        asm volatile("cp.async.cg.shared.global [%0], [%1], 16;"
                     :: "r"(dst), "l"(__cvta_generic_to_global(src + k2 * 128)));
    }
    asm volatile("cp.async.commit_group;" ::: "memory");
}
static __device__ __forceinline__ void a_stage(char* smem, const float* phic,
                                               int wid, int lane) {
    const float4* g4 = reinterpret_cast<const float4*>(phic);
    #pragma unroll
    for (int s = 0; s < 8; ++s) {
        int idx = wid * 256 + 32 * s + lane;
        float4 v = g4[idx];
        int mrow = idx >> 4;
        int q    = idx & 15;
        uint32_t off = (uint32_t)mrow * 128 +
                       ((uint32_t)((q >> 1) ^ (mrow & 7)) << 4) + ((q & 1) << 3);
        uint32_t hx, lx, hy, ly;
        cvt_split(v.x, v.y, hx, lx);
        cvt_split(v.z, v.w, hy, ly);
        *reinterpret_cast<uint2*>(smem + SM_AH + off) = make_uint2(hx, hy);
        *reinterpret_cast<uint2*>(smem + SM_AL + off) = make_uint2(lx, ly);
    }
}

// ---------------------------------------------------------------------------
__global__ void __launch_bounds__(64) prep_kernel(const float* __restrict__ W) {
    int T0 = blockIdx.x;
    for (int idx = threadIdx.x; idx < 1024; idx += 64) {
        int lane = idx & 31;
        int nt   = (idx >> 5) & 7;
        int kk   = idx >> 8;
        int n    = 8 * nt + (lane >> 2);
        int k0   = 16 * kk + (lane & 3) * 2;
        float w00 = W[(((k0     + T0) & 63) << 6) + n];
        float w01 = W[(((k0 + 1 + T0) & 63) << 6) + n];
        float w10 = W[(((k0 + 8 + T0) & 63) << 6) + n];
        float w11 = W[(((k0 + 9 + T0) & 63) << 6) + n];
        uint32_t h0, l0, h1, l1;
        cvt_split(w00, w01, h0, l0);
        cvt_split(w10, w11, h1, l1);
        BV[T0 * 1024 + idx] = make_uint4(h0, h1, l0, l1);
    }
}

// ---------------------------------------------------------------------------
// Main: persistent. Block 0: LU(W) + logDet tail. Blocks 1..888: configs
// i = blk-1, blk-1+888, ...  (warp w: rows 16w..16w+15 of each config).
// ---------------------------------------------------------------------------
__global__ void __launch_bounds__(128, 6) main_kernel(
    const float* __restrict__ phi, const float* __restrict__ W,
    const float* __restrict__ b, float* __restrict__ out, int write_logdet)
{
    extern __shared__ char smem[];
    uint32_t sbase = smem_u32(smem);
    int tid  = threadIdx.x;
    int wid  = tid >> 5;
    int lane = tid & 31;

    if (blockIdx.x == 0) {   // ---------------- LU block ----------------
        float (*A)[65] = reinterpret_cast<float(*)[65]>(smem);
        float* m   = reinterpret_cast<float*>(smem + 16640);
        float* rv  = reinterpret_cast<float*>(smem + 16896);
        int*   ri  = reinterpret_cast<int*>(smem + 16904);
        float* sld = reinterpret_cast<float*>(smem + 16912);

        for (int idx = tid; idx < 64 * 64; idx += 128)
            A[idx >> 6][idx & 63] = W[idx];
        __syncthreads();

        float ld = 0.0f;
        for (int k = 0; k < 64; ++k) {
            if (tid < 64) {
                float v  = (tid >= k) ? fabsf(A[tid][k]) : -1.0f;
                int   vi = tid;
                #pragma unroll
                for (int off = 16; off > 0; off >>= 1) {
                    float ov = __shfl_down_sync(0xffffffffu, v,  off);
                    int   oi = __shfl_down_sync(0xffffffffu, vi, off);
                    if (ov > v) { v = ov; vi = oi; }
                }
                if ((tid & 31) == 0) { rv[tid >> 5] = v; ri[tid >> 5] = vi; }
            }
            __syncthreads();
            int p = (rv[1] > rv[0]) ? ri[1] : ri[0];
            if (tid < 64 && p != k) {
                float t1 = A[k][tid], t2 = A[p][tid];
                A[k][tid] = t2; A[p][tid] = t1;
            }
            __syncthreads();
            float piv = A[k][k];
            if (tid < 64) {
                ld += logf(fabsf(piv));
                if (tid > k) m[tid] = A[tid][k] / piv;
            }
            __syncthreads();
            if (tid < 64 && tid > k) {
                float akj = A[k][tid];
                for (int r = k + 1; r < 64; ++r)
                    A[r][tid] -= m[r] * akj;
            }
            __syncthreads();
        }
        if (write_logdet) {
            if (tid == 0) *sld = ld;
            __syncthreads();
            float val = (float)NT * (*sld);
            float* tail = out + (size_t)NCONF * NT * NX;
            for (int idx = tid; idx < NCONF; idx += 128)
                tail[idx] = val;
        }
        return;
    }

    int i = blockIdx.x - 1;                         // first config
    const float* phic = phi + (size_t)i * (NT * NX);

    // --- prologue for first config ---
    int T0;
    {
        float2 u0 = *reinterpret_cast<const float2*>(phic + (size_t)lane * NX);
        float2 u1 = *reinterpret_cast<const float2*>(phic + (size_t)(lane + 32) * NX);
        T0 = t0_reduce(u0, u1, lane);
    }
    b_issue(sbase, T0, tid);
    a_stage(smem, phic, wid, lane);
    __syncwarp();
    asm volatile("cp.async.wait_group 0;" ::: "memory");
    __syncthreads();

    int mrel = (lane & 7) + ((lane >> 3) & 1) * 8;
    int csel = (lane >> 4) & 1;
    int mm   = 16 * wid + mrel;
    int qrow = lane >> 2;
    int qcol = (lane & 3) * 2;

    for (;;) {
        int offs = (64 - T0) & 63;

        // --- MMA loop ---
        const uint4* bBase = reinterpret_cast<const uint4*>(smem + SM_B) + lane;
        float d[8][4];
        #pragma unroll
        for (int nt = 0; nt < 8; ++nt)
            #pragma unroll
            for (int e = 0; e < 4; ++e) d[nt][e] = 0.0f;

        #pragma unroll
        for (int kk = 0; kk < 4; ++kk) {
            uint32_t co = (uint32_t)((kk * 2 + csel) ^ (mm & 7)) << 4;
            uint32_t rowoff = (uint32_t)mm * 128 + co;
            uint32_t ahi[4], alo[4];
            ldsm_x4(ahi[0], ahi[1], ahi[2], ahi[3], sbase + SM_AH + rowoff);
            ldsm_x4(alo[0], alo[1], alo[2], alo[3], sbase + SM_AL + rowoff);
            const uint4* bk = bBase + kk * 256;
            #pragma unroll
            for (int nt = 0; nt < 8; ++nt) {
                uint4 w = bk[nt * 32];
                mma_bf16(d[nt], ahi[0], ahi[1], ahi[2], ahi[3], w.x, w.y);
                mma_bf16(d[nt], alo[0], alo[1], alo[2], alo[3], w.x, w.y);
                mma_bf16(d[nt], ahi[0], ahi[1], ahi[2], ahi[3], w.z, w.w);
            }
        }
        __syncthreads();   // A consumed by all warps (B region disjoint from stage)

        int inext = i + GRIDC;
        bool more = (inext < NCONF);
        const float* phin = phi + (size_t)inext * (NT * NX);

        // --- epilogue: +bias, roll into stage; accumulators die here ---
        float* st = reinterpret_cast<float*>(smem) + wid * (16 * 68);
        #pragma unroll
        for (int nt = 0; nt < 8; ++nt) {
            int jb = 8 * nt + qcol;
            float2 bias = __ldg(reinterpret_cast<const float2*>(b + jb));
            int j0 = (jb + offs) & 63;
            int j1 = (jb + 1 + offs) & 63;
            st[qrow * 68 + j0]       = d[nt][0] + bias.x;
            st[qrow * 68 + j1]       = d[nt][1] + bias.y;
            st[(qrow + 8) * 68 + j0] = d[nt][2] + bias.x;
            st[(qrow + 8) * 68 + j1] = d[nt][3] + bias.y;
        }

        // issue next-config T0 loads early (regs freed by stage writes)
        float2 w0, w1;
        if (more) {
            w0 = *reinterpret_cast<const float2*>(phin + (size_t)lane * NX);
            w1 = *reinterpret_cast<const float2*>(phin + (size_t)(lane + 32) * NX);
        }
        __syncwarp();

        // --- flush: coalesced float4 rows ---
        float* obase = out + (size_t)i * (NT * NX) + (size_t)(16 * wid) * NX;
        #pragma unroll
        for (int it = 0; it < 8; ++it) {
            int r  = it * 2 + (lane >> 4);
            int c4 = (lane & 15) * 4;
            float4 v = *reinterpret_cast<const float4*>(st + r * 68 + c4);
            *reinterpret_cast<float4*>(obase + (size_t)r * NX + c4) = v;
        }

        if (!more) break;

        // next-config B prefetch (B region free; stage/A protected by next bar)
        T0 = t0_reduce(w0, w1, lane);
        b_issue(sbase, T0, tid);
        __syncthreads();   // all flushes done -> stage/A region writable

        i = inext;
        phic = phin;
        a_stage(smem, phic, wid, lane);
        __syncwarp();
        asm volatile("cp.async.wait_group 0;" ::: "memory");
        __syncthreads();
    }
}

// ---------------------------------------------------------------------------
extern "C" void kernel_launch(void* const* d_in, const int* in_sizes, int n_in,
                              void* d_out, int out_size) {
    const float* phi = nullptr;
    const float* W   = nullptr;
    const float* b   = nullptr;
    for (int k = 0; k < n_in; ++k) {
        if      (in_sizes[k] == NCONF * NT * NX) phi = (const float*)d_in[k];
        else if (in_sizes[k] == NX * NX)         W   = (const float*)d_in[k];
        else if (in_sizes[k] == NX)              b   = (const float*)d_in[k];
    }
    float* out = (float*)d_out;
    int write_logdet = (out_size >= NCONF * NT * NX + NCONF) ? 1 : 0;

    cudaFuncSetAttribute(main_kernel, cudaFuncAttributeMaxDynamicSharedMemorySize, SM_TOTAL);
    prep_kernel<<<64, 64>>>(W);
    main_kernel<<<GRIDC + 1, 128, SM_TOTAL>>>(phi, W, b, out, write_logdet);
}